// round 6
// baseline (speedup 1.0000x reference)
#include <cuda_runtime.h>
#include <cstdint>

typedef unsigned long long u64;

#define KOUT 512
#define NT   512
#define CAP  2048
#define NB   4096
#define BPT  (NB / NT)     // 8
#define SSMP 1024          // samples

__device__ __forceinline__ unsigned fkey(float f) {
    unsigned u = __float_as_uint(f);
    return u ^ ((u & 0x80000000u) ? 0xFFFFFFFFu : 0x80000000u);
}
__device__ __forceinline__ float finv(unsigned v) {
    unsigned u = v ^ ((v & 0x80000000u) ? 0x80000000u : 0xFFFFFFFFu);
    return __uint_as_float(u);
}
__device__ __forceinline__ u64 pack(float x, float y) {
    return ((u64)fkey(x) << 32) | (u64)fkey(y);
}

struct Sh {
    u64 buf[CAP];
    int hist[NB];
    int wsum[NT / 32];
    int cnt, pivot, below;
};

// smallest bin p with cumsum >= target; sets sh.pivot / sh.below
__device__ void find_pivot(Sh& sh, int target) {
    const int t = threadIdx.x;
    const int base = t * BPT;
    int local = 0;
#pragma unroll
    for (int j = 0; j < BPT; j++) local += sh.hist[base + j];
    const int lane = t & 31, warp = t >> 5;
    int incl = local;
#pragma unroll
    for (int o = 1; o < 32; o <<= 1) {
        int v = __shfl_up_sync(0xFFFFFFFFu, incl, o);
        if (lane >= o) incl += v;
    }
    if (lane == 31) sh.wsum[warp] = incl;
    __syncthreads();
    if (t == 0) {
        int acc = 0;
#pragma unroll
        for (int i = 0; i < NT / 32; i++) { int v = sh.wsum[i]; sh.wsum[i] = acc; acc += v; }
    }
    __syncthreads();
    const int excl = sh.wsum[warp] + incl - local;
    if (excl < target && excl + local >= target) {
        int c = excl;
#pragma unroll
        for (int j = 0; j < BPT; j++) {
            int h = sh.hist[base + j];
            if (c + h >= target) { sh.pivot = base + j; sh.below = c; break; }
            c += h;
        }
    }
    __syncthreads();
}

__device__ __forceinline__ void push(Sh& sh, u64 k) {
    int pos = atomicAdd(&sh.cnt, 1);
    if (pos < CAP) sh.buf[pos] = k;
}

// hot pass: gather all points with x <= hi_f (float compare, no barriers)
// unrolled x2 for MLP: two independent LDG.128 in flight per thread
__device__ void gather_f(Sh& sh, const float2* __restrict__ base, int n, float hi_f) {
    const int t = threadIdx.x;
    int i = 2 * t;
    for (; i + 2 * NT + 1 < n; i += 4 * NT) {
        float4 a = *(const float4*)(base + i);
        float4 c = *(const float4*)(base + i + 2 * NT);
        if (a.x <= hi_f) push(sh, pack(a.x, a.y));
        if (a.z <= hi_f) push(sh, pack(a.z, a.w));
        if (c.x <= hi_f) push(sh, pack(c.x, c.y));
        if (c.z <= hi_f) push(sh, pack(c.z, c.w));
    }
    for (; i + 1 < n; i += 2 * NT) {
        float4 a = *(const float4*)(base + i);
        if (a.x <= hi_f) push(sh, pack(a.x, a.y));
        if (a.z <= hi_f) push(sh, pack(a.z, a.w));
    }
    if (i < n) {
        float2 c = base[i];
        if (c.x <= hi_f) push(sh, pack(c.x, c.y));
    }
}

// exact-fkey gather for the fallback path
__device__ void gather_k(Sh& sh, const float2* __restrict__ base, int n, unsigned T) {
    const int t = threadIdx.x;
    int i = 2 * t;
    for (; i + 1 < n; i += 2 * NT) {
        float4 v = *(const float4*)(base + i);
        if (fkey(v.x) <= T) push(sh, pack(v.x, v.y));
        if (fkey(v.z) <= T) push(sh, pack(v.z, v.w));
    }
    if (i < n) {
        float2 c = base[i];
        if (fkey(c.x) <= T) push(sh, pack(c.x, c.y));
    }
}

__device__ void bitonic(u64* a, int P) {
    const int t = threadIdx.x;
    for (int size = 2; size <= P; size <<= 1) {
        for (int stride = size >> 1; stride > 0; stride >>= 1) {
            for (int i = t; i < P; i += NT) {
                int j = i ^ stride;
                if (j > i) {
                    u64 x = a[i], y = a[j];
                    bool up = ((i & size) == 0);
                    if ((x > y) == up) { a[i] = y; a[j] = x; }
                }
            }
            __syncthreads();
        }
    }
}

__global__ __launch_bounds__(NT)
void topk_sample_kernel(const float2* __restrict__ corners,
                        const int*    __restrict__ lengths,
                        float2*       __restrict__ out,
                        int M) {
    __shared__ Sh sh;
    const int b = blockIdx.x;
    const int t = threadIdx.x;
    const int n  = lengths[b];
    const int kk = n < KOUT ? n : KOUT;
    float2* outp = out + (size_t)b * KOUT;

    if (kk == 0) { outp[t] = make_float2(0.f, 0.f); return; }

    const float2* base = corners + (size_t)b * M;

    if (t == 0) sh.cnt = 0;

    if (n <= CAP) {
        // everything fits: gather all, no threshold needed
        __syncthreads();
        gather_f(sh, base, n, __int_as_float(0x7F800000));  // +inf accepts all
    } else {
        // ---- Phase A: sample histogram -> threshold ----
        for (int i = t; i < NB; i += NT) sh.hist[i] = 0;
        __syncthreads();
        for (int s = t; s < SSMP; s += NT) {
            long long pos = ((long long)s * n) / SSMP;
            float x = base[pos].x;
            atomicAdd(&sh.hist[fkey(x) >> 20], 1);
        }
        __syncthreads();
        float q = (float)kk / (float)n;
        float m = (float)SSMP * q;
        int ts = (int)(m + 3.0f * sqrtf(m * (1.0f - q)) + 16.5f);
        if (ts < 1) ts = 1;
        if (ts > SSMP) ts = SSMP;
        find_pivot(sh, ts);
        unsigned hiK = (((unsigned)sh.pivot + 1u) << 20) - 1u;
        float hi_f = finv(hiK);
        // ---- Phase B: single filtered pass ----
        gather_f(sh, base, n, hi_f);
    }
    __syncthreads();

    if (sh.cnt < kk || sh.cnt > CAP) {
        // ---- Fallback: exact 3-level histogram refinement (rare) ----
        for (int i = t; i < NB; i += NT) sh.hist[i] = 0;
        __syncthreads();
        for (int i = t; i < n; i += NT) atomicAdd(&sh.hist[fkey(base[i].x) >> 20], 1);
        __syncthreads();
        find_pivot(sh, kk);
        int d0 = sh.pivot, below0 = sh.below, in0 = sh.hist[d0];
        unsigned T;
        if (below0 + in0 <= CAP) {
            T = ((unsigned)d0 << 20) | 0xFFFFFu;
        } else {
            __syncthreads();
            for (int i = t; i < NB; i += NT) sh.hist[i] = 0;
            __syncthreads();
            for (int i = t; i < n; i += NT) {
                unsigned u = fkey(base[i].x);
                if ((u >> 20) == (unsigned)d0) atomicAdd(&sh.hist[(u >> 8) & 0xFFFu], 1);
            }
            __syncthreads();
            find_pivot(sh, kk - below0);
            int d1 = sh.pivot, below1 = sh.below, in1 = sh.hist[d1];
            if (below0 + below1 + in1 <= CAP) {
                T = ((unsigned)d0 << 20) | ((unsigned)d1 << 8) | 0xFFu;
            } else {
                __syncthreads();
                for (int i = t; i < NB; i += NT) sh.hist[i] = 0;
                __syncthreads();
                const unsigned pref = ((unsigned)d0 << 12) | (unsigned)d1;
                for (int i = t; i < n; i += NT) {
                    unsigned u = fkey(base[i].x);
                    if ((u >> 8) == pref) atomicAdd(&sh.hist[u & 0xFFu], 1);
                }
                __syncthreads();
                find_pivot(sh, kk - below0 - below1);
                T = ((unsigned)d0 << 20) | ((unsigned)d1 << 8) | (unsigned)sh.pivot;
            }
        }
        if (t == 0) sh.cnt = 0;
        __syncthreads();
        gather_k(sh, base, n, T);
        __syncthreads();
    }

    int C = sh.cnt < CAP ? sh.cnt : CAP;
    int P = 1; while (P < C) P <<= 1;
    if (P < 2) P = 2;
    for (int i = C + t; i < P; i += NT) sh.buf[i] = ~0ull;
    __syncthreads();
    bitonic(sh.buf, P);

    float2 o = make_float2(0.f, 0.f);
    if (t < kk) {
        u64 k = sh.buf[t];
        o = make_float2(finv((unsigned)(k >> 32)), finv((unsigned)k));
    }
    outp[t] = o;
}

extern "C" void kernel_launch(void* const* d_in, const int* in_sizes, int n_in,
                              void* d_out, int out_size) {
    const float2* corners = (const float2*)d_in[0];
    const int*    lengths = (const int*)d_in[1];
    float2*       out     = (float2*)d_out;
    const int B = in_sizes[1];
    const int M = in_sizes[0] / (B * 2);
    topk_sample_kernel<<<B, NT>>>(corners, lengths, out, M);
}

// round 7
// speedup vs baseline: 1.3793x; 1.3793x over previous
#include <cuda_runtime.h>
#include <cstdint>

typedef unsigned long long u64;

#define KOUT    512
#define NT      512
#define CAP     2048
#define NB      4096
#define BPT     (NB / NT)   // 8
#define SSMP    1024
#define SORTMAX 1024

__device__ unsigned g_ticket;
__global__ void reset_ticket() { g_ticket = 0; }

__device__ __forceinline__ unsigned fkey(float f) {
    unsigned u = __float_as_uint(f);
    return u ^ ((u & 0x80000000u) ? 0xFFFFFFFFu : 0x80000000u);
}
__device__ __forceinline__ float finv(unsigned v) {
    unsigned u = v ^ ((v & 0x80000000u) ? 0x80000000u : 0xFFFFFFFFu);
    return __uint_as_float(u);
}
__device__ __forceinline__ u64 pack(float x, float y) {
    return ((u64)fkey(x) << 32) | (u64)fkey(y);
}

struct Sh {
    u64 buf[CAP];                               // 16 KB candidates
    union { int hist[NB]; u64 buf2[CAP]; };     // 16 KB hist / compact target
    int wsum[NT / 32];
    int cnt, pivot, below, batch;
};

// smallest bin p with cumsum >= target; sets sh.pivot / sh.below
__device__ void find_pivot(Sh& sh, int target) {
    const int t = threadIdx.x;
    const int base = t * BPT;
    int local = 0;
#pragma unroll
    for (int j = 0; j < BPT; j++) local += sh.hist[base + j];
    const int lane = t & 31, warp = t >> 5;
    int incl = local;
#pragma unroll
    for (int o = 1; o < 32; o <<= 1) {
        int v = __shfl_up_sync(0xFFFFFFFFu, incl, o);
        if (lane >= o) incl += v;
    }
    if (lane == 31) sh.wsum[warp] = incl;
    __syncthreads();
    if (t == 0) {
        int acc = 0;
#pragma unroll
        for (int i = 0; i < NT / 32; i++) { int v = sh.wsum[i]; sh.wsum[i] = acc; acc += v; }
    }
    __syncthreads();
    const int excl = sh.wsum[warp] + incl - local;
    if (excl < target && excl + local >= target) {
        int c = excl;
#pragma unroll
        for (int j = 0; j < BPT; j++) {
            int h = sh.hist[base + j];
            if (c + h >= target) { sh.pivot = base + j; sh.below = c; break; }
            c += h;
        }
    }
    __syncthreads();
}

__device__ __forceinline__ void push(Sh& sh, u64 k) {
    int pos = atomicAdd(&sh.cnt, 1);
    if (pos < CAP) sh.buf[pos] = k;
}

// hot pass: gather all points with x <= hi_f (no barriers)
__device__ void gather_f(Sh& sh, const float2* __restrict__ base, int n, float hi_f) {
    const int t = threadIdx.x;
    int i = 2 * t;
    for (; i + 2 * NT + 1 < n; i += 4 * NT) {
        float4 a = *(const float4*)(base + i);
        float4 c = *(const float4*)(base + i + 2 * NT);
        if (fminf(a.x, a.z) <= hi_f) {
            if (a.x <= hi_f) push(sh, pack(a.x, a.y));
            if (a.z <= hi_f) push(sh, pack(a.z, a.w));
        }
        if (fminf(c.x, c.z) <= hi_f) {
            if (c.x <= hi_f) push(sh, pack(c.x, c.y));
            if (c.z <= hi_f) push(sh, pack(c.z, c.w));
        }
    }
    for (; i + 1 < n; i += 2 * NT) {
        float4 a = *(const float4*)(base + i);
        if (a.x <= hi_f) push(sh, pack(a.x, a.y));
        if (a.z <= hi_f) push(sh, pack(a.z, a.w));
    }
    if (i < n) {
        float2 c = base[i];
        if (c.x <= hi_f) push(sh, pack(c.x, c.y));
    }
}

// exact-fkey gather for the fallback path
__device__ void gather_k(Sh& sh, const float2* __restrict__ base, int n, unsigned T) {
    const int t = threadIdx.x;
    int i = 2 * t;
    for (; i + 1 < n; i += 2 * NT) {
        float4 v = *(const float4*)(base + i);
        if (fkey(v.x) <= T) push(sh, pack(v.x, v.y));
        if (fkey(v.z) <= T) push(sh, pack(v.z, v.w));
    }
    if (i < n) {
        float2 c = base[i];
        if (fkey(c.x) <= T) push(sh, pack(c.x, c.y));
    }
}

__device__ void bitonic(u64* a, int P) {
    const int t = threadIdx.x;
    for (int size = 2; size <= P; size <<= 1) {
        for (int stride = size >> 1; stride > 0; stride >>= 1) {
            for (int i = t; i < P; i += NT) {
                int j = i ^ stride;
                if (j > i) {
                    u64 x = a[i], y = a[j];
                    bool up = ((i & size) == 0);
                    if ((x > y) == up) { a[i] = y; a[j] = x; }
                }
            }
            __syncthreads();
        }
    }
}

__global__ __launch_bounds__(NT, 3)
void topk_kernel(const float2* __restrict__ corners,
                 const int*    __restrict__ lengths,
                 float2*       __restrict__ out,
                 int M, int B) {
    __shared__ Sh sh;
    const int t = threadIdx.x;

    for (;;) {
        if (t == 0) sh.batch = atomicAdd(&g_ticket, 1);
        __syncthreads();
        const int b = sh.batch;
        if (b >= B) return;

        const int n  = lengths[b];
        const int kk = n < KOUT ? n : KOUT;
        float2* outp = out + (size_t)b * KOUT;

        if (kk == 0) {
            outp[t] = make_float2(0.f, 0.f);
            __syncthreads();
            continue;
        }
        const float2* base = corners + (size_t)b * M;

        if (t == 0) sh.cnt = 0;

        if (n <= CAP) {
            __syncthreads();
            gather_f(sh, base, n, __int_as_float(0x7F800000));   // gather all
        } else {
            // ---- Phase A: sample histogram -> x threshold ----
            for (int i = t; i < NB; i += NT) sh.hist[i] = 0;
            __syncthreads();
            for (int s = t; s < SSMP; s += NT) {
                int pos = (int)(((u64)s * (unsigned)n) >> 10);   // s*n/1024
                atomicAdd(&sh.hist[fkey(base[pos].x) >> 20], 1);
            }
            __syncthreads();
            float q = (float)kk / (float)n;
            float m = (float)SSMP * q;
            int ts = (int)(m + 3.0f * sqrtf(m * (1.0f - q)) + 16.5f);
            if (ts < 1) ts = 1;
            if (ts > SSMP) ts = SSMP;
            find_pivot(sh, ts);
            unsigned hiK = (((unsigned)sh.pivot + 1u) << 20) - 1u;
            float hi_f = finv(hiK);
            gather_f(sh, base, n, hi_f);
        }
        __syncthreads();

        if (sh.cnt < kk || sh.cnt > CAP) {
            // ---- Fallback: exact 3-level histogram refinement (rare) ----
            for (int i = t; i < NB; i += NT) sh.hist[i] = 0;
            __syncthreads();
            for (int i = t; i < n; i += NT) atomicAdd(&sh.hist[fkey(base[i].x) >> 20], 1);
            __syncthreads();
            find_pivot(sh, kk);
            int d0 = sh.pivot, below0 = sh.below, in0 = sh.hist[d0];
            unsigned T;
            if (below0 + in0 <= CAP) {
                T = ((unsigned)d0 << 20) | 0xFFFFFu;
            } else {
                __syncthreads();
                for (int i = t; i < NB; i += NT) sh.hist[i] = 0;
                __syncthreads();
                for (int i = t; i < n; i += NT) {
                    unsigned u = fkey(base[i].x);
                    if ((u >> 20) == (unsigned)d0) atomicAdd(&sh.hist[(u >> 8) & 0xFFFu], 1);
                }
                __syncthreads();
                find_pivot(sh, kk - below0);
                int d1 = sh.pivot, below1 = sh.below, in1 = sh.hist[d1];
                if (below0 + below1 + in1 <= CAP) {
                    T = ((unsigned)d0 << 20) | ((unsigned)d1 << 8) | 0xFFu;
                } else {
                    __syncthreads();
                    for (int i = t; i < NB; i += NT) sh.hist[i] = 0;
                    __syncthreads();
                    const unsigned pref = ((unsigned)d0 << 12) | (unsigned)d1;
                    for (int i = t; i < n; i += NT) {
                        unsigned u = fkey(base[i].x);
                        if ((u >> 8) == pref) atomicAdd(&sh.hist[u & 0xFFu], 1);
                    }
                    __syncthreads();
                    find_pivot(sh, kk - below0 - below1);
                    T = ((unsigned)d0 << 20) | ((unsigned)d1 << 8) | (unsigned)sh.pivot;
                }
            }
            if (t == 0) sh.cnt = 0;
            __syncthreads();
            gather_k(sh, base, n, T);
            __syncthreads();
        }

        int C = sh.cnt < CAP ? sh.cnt : CAP;
        u64* sbuf = sh.buf;

        // ---- Selection: cut candidate set to <= SORTMAX before sorting ----
        if (C > SORTMAX) {
            for (int i = t; i < NB; i += NT) sh.hist[i] = 0;
            __syncthreads();
            for (int i = t; i < C; i += NT)
                atomicAdd(&sh.hist[(int)(sh.buf[i] >> 52)], 1);
            __syncthreads();
            find_pivot(sh, kk);
            int p0 = sh.pivot, below0 = sh.below, in0 = sh.hist[p0];
            int keepN = below0 + in0;
            int p1 = 0; bool two = false;
            if (keepN > SORTMAX) {
                __syncthreads();
                for (int i = t; i < NB; i += NT) sh.hist[i] = 0;
                __syncthreads();
                for (int i = t; i < C; i += NT) {
                    u64 k = sh.buf[i];
                    if ((int)(k >> 52) == p0)
                        atomicAdd(&sh.hist[(int)((k >> 40) & 0xFFFu)], 1);
                }
                __syncthreads();
                find_pivot(sh, kk - below0);
                p1 = sh.pivot;
                keepN = below0 + sh.below + sh.hist[p1];
                two = true;
            }
            if (keepN <= SORTMAX) {
                if (t == 0) sh.cnt = 0;
                __syncthreads();
                for (int i = t; i < C; i += NT) {
                    u64 k = sh.buf[i];
                    int hb = (int)(k >> 52);
                    bool keep = two ? (hb < p0 || (hb == p0 && (int)((k >> 40) & 0xFFFu) <= p1))
                                    : (hb <= p0);
                    if (keep) { int pos = atomicAdd(&sh.cnt, 1); sh.buf2[pos] = k; }
                }
                __syncthreads();
                C = sh.cnt;
                sbuf = sh.buf2;
            }
            // else: pathological duplicates — sort full buf (rare)
        }

        int P = 1; while (P < C) P <<= 1;
        if (P < 2) P = 2;
        for (int i = C + t; i < P; i += NT) sbuf[i] = ~0ull;
        __syncthreads();
        bitonic(sbuf, P);

        float2 o = make_float2(0.f, 0.f);
        if (t < kk) {
            u64 k = sbuf[t];
            o = make_float2(finv((unsigned)(k >> 32)), finv((unsigned)k));
        }
        outp[t] = o;
        __syncthreads();   // protect sh before next ticket
    }
}

extern "C" void kernel_launch(void* const* d_in, const int* in_sizes, int n_in,
                              void* d_out, int out_size) {
    const float2* corners = (const float2*)d_in[0];
    const int*    lengths = (const int*)d_in[1];
    float2*       out     = (float2*)d_out;
    const int B = in_sizes[1];
    const int M = in_sizes[0] / (B * 2);
    reset_ticket<<<1, 1>>>();
    topk_kernel<<<B, NT>>>(corners, lengths, out, M, B);
}